// round 12
// baseline (speedup 1.0000x reference)
#include <cuda_runtime.h>
#include <math.h>
#include <stdint.h>

#define NB 32
#define NS 8192
#define ND 256
#define NCHUNK 64          // blocks per batch in main pass
#define POS_PER_BLOCK 128  // rows per block
#define TILE_ROWS 16       // rows per cp.async tile
#define NTILES (POS_PER_BLOCK / TILE_ROWS)   // 8
#define NPRE 16            // k_pre reduction split
#define EXP_OFF 48.0f      // fixed softmax offset (energies << 48+88)

// ---------------- scratch (no allocation allowed) ----------------
__device__ float g_Vp[NB * NPRE * ND];     // partial v[b] (k_pre out)
__device__ float g_V[NB * ND];             // final v[b]   (k_pre2 out)
__device__ float g_c0[NB];                 // ht[b] . Wa_b
__device__ float g_PL[NB * NCHUNK];        // per-block partial sum (fixed offset)
__device__ float g_PA[NB * NCHUNK * ND];   // per-block partial weighted row-sum

// ---------------- cp.async helpers ----------------
__device__ __forceinline__ void cp16(uint32_t dst, const void* src) {
    asm volatile("cp.async.cg.shared.global [%0], [%1], 16;\n" :: "r"(dst), "l"(src));
}
__device__ __forceinline__ void cp_commit() {
    asm volatile("cp.async.commit_group;\n" ::: "memory");
}
template <int N>
__device__ __forceinline__ void cp_wait() {
    asm volatile("cp.async.wait_group %0;\n" :: "n"(N) : "memory");
}

// ---------------- K1: partial v[b], c0[b] (16-way split over d) ----------
__global__ void __launch_bounds__(256)
k_pre(const float* __restrict__ ht,
      const float* __restrict__ Wa_w,
      const float* __restrict__ Wa_b) {
    int g = blockIdx.x, b = blockIdx.y, t = threadIdx.x;
    __shared__ float sh[16];
    if (t < 16) sh[t] = ht[b * ND + g * 16 + t];
    __syncthreads();
    const float* Wp = Wa_w + (size_t)(g * 16) * ND + t;
    float acc = 0.f;
    #pragma unroll
    for (int d = 0; d < 16; d++)                      // 16 loads, all in flight
        acc = fmaf(sh[d], Wp[(size_t)d * ND], acc);
    g_Vp[(b * NPRE + g) * ND + t] = acc;

    if (g == 0) {   // c0 = ht . Wa_b
        __shared__ float red[ND];
        red[t] = ht[b * ND + t] * Wa_b[t];
        __syncthreads();
        for (int s = 128; s > 0; s >>= 1) {
            if (t < s) red[t] += red[t + s];
            __syncthreads();
        }
        if (t == 0) g_c0[b] = red[0];
    }
}

// ---------------- K1b: fold 16 partials -> g_V (L2-hot, tiny) ------------
__global__ void __launch_bounds__(256)
k_pre2() {
    int b = blockIdx.x, t = threadIdx.x;
    const float* p = g_Vp + (size_t)b * NPRE * ND + t;
    float a0 = 0.f, a1 = 0.f, a2 = 0.f, a3 = 0.f;
    #pragma unroll
    for (int g = 0; g < NPRE; g += 4) {               // 16 loads in flight
        a0 += p[(g + 0) * ND];
        a1 += p[(g + 1) * ND];
        a2 += p[(g + 2) * ND];
        a3 += p[(g + 3) * ND];
    }
    g_V[b * ND + t] = (a0 + a1) + (a2 + a3);
}

// ---------------- K2: 2-stage cp.async pipeline (R10/R11 exact) ----------
__global__ void __launch_bounds__(256, 4)
k_main(const float* __restrict__ hs, const int* __restrict__ slen,
       float* __restrict__ alpha) {
    __shared__ __align__(16) float sbuf[2][TILE_ROWS * ND];   // 2 x 16KB
    __shared__ float sA[8][ND];                                // 8KB
    __shared__ float sL[8];

    int chunk = blockIdx.x, b = blockIdx.y;
    int tid = threadIdx.x, w = tid >> 5, lane = tid & 31;
    int len = slen[b];
    int len_eff = (len == 0) ? NS : len;
    float off = (len == 0) ? -10000.f : EXP_OFF;

    if (chunk * POS_PER_BLOCK >= len_eff) return;

    const float* gsrc = hs + ((size_t)b * NS + chunk * POS_PER_BLOCK) * ND;
    uint32_t sb = (uint32_t)__cvta_generic_to_shared(&sbuf[0][0]);

    // stage tile 0
    {
        uint32_t dst = sb;
        const char* src = (const char*)gsrc;
        #pragma unroll
        for (int k = 0; k < 4; k++)
            cp16(dst + (tid + k * 256) * 16, src + (size_t)(tid + k * 256) * 16);
        cp_commit();
    }

    // v fragments: 2 loads from final g_V (L2-hot)
    float c0 = g_c0[b];
    const float4* v4 = (const float4*)(g_V + b * ND);
    float4 va = v4[lane], vb = v4[lane + 32];

    float Lsum = 0.f;
    float4 Aa = make_float4(0.f, 0.f, 0.f, 0.f);
    float4 Ab = make_float4(0.f, 0.f, 0.f, 0.f);
    int s0 = chunk * POS_PER_BLOCK;

    #pragma unroll 1
    for (int t = 0; t < NTILES; t++) {
        if (t < NTILES - 1) {            // stage next tile into other buffer
            uint32_t dst = sb + ((t + 1) & 1) * (TILE_ROWS * ND * 4);
            const char* src = (const char*)(gsrc + (t + 1) * TILE_ROWS * ND);
            #pragma unroll
            for (int k = 0; k < 4; k++)
                cp16(dst + (tid + k * 256) * 16, src + (size_t)(tid + k * 256) * 16);
            cp_commit();
            cp_wait<1>();
        } else {
            cp_wait<0>();
        }
        __syncthreads();

        // compute: warp w handles rows 2w, 2w+1 of this tile
        const float* sp = sbuf[t & 1] + (2 * w) * ND;
        float4 r1a = ((const float4*)sp)[lane];
        float4 r1b = ((const float4*)sp)[lane + 32];
        float4 r2a = ((const float4*)sp)[64 + lane];
        float4 r2b = ((const float4*)sp)[64 + lane + 32];

        float p1 = r1a.x*va.x + r1a.y*va.y + r1a.z*va.z + r1a.w*va.w
                 + r1b.x*vb.x + r1b.y*vb.y + r1b.z*vb.z + r1b.w*vb.w;
        float p2 = r2a.x*va.x + r2a.y*va.y + r2a.z*va.z + r2a.w*va.w
                 + r2b.x*vb.x + r2b.y*vb.y + r2b.z*vb.z + r2b.w*vb.w;
        #pragma unroll
        for (int o = 16; o > 0; o >>= 1) {
            p1 += __shfl_xor_sync(0xffffffffu, p1, o);
            p2 += __shfl_xor_sync(0xffffffffu, p2, o);
        }
        int s = s0 + t * TILE_ROWS + 2 * w;
        float e1 = p1 + c0, e2 = p2 + c0;
        e1 = (e1 > 0.f) ? e1 : 0.2f * e1;            // leaky relu
        e2 = (e2 > 0.f) ? e2 : 0.2f * e2;
        if (s + 0 >= len) e1 = -10000.f;             // length mask
        if (s + 1 >= len) e2 = -10000.f;
        if (lane == 0)
            *(float2*)(alpha + (size_t)b * NS + s) = make_float2(e1, e2);

        float q1 = __expf(e1 - off);                 // fixed offset softmax
        float q2 = __expf(e2 - off);
        Lsum += q1 + q2;
        Aa.x = fmaf(q2, r2a.x, fmaf(q1, r1a.x, Aa.x));
        Aa.y = fmaf(q2, r2a.y, fmaf(q1, r1a.y, Aa.y));
        Aa.z = fmaf(q2, r2a.z, fmaf(q1, r1a.z, Aa.z));
        Aa.w = fmaf(q2, r2a.w, fmaf(q1, r1a.w, Aa.w));
        Ab.x = fmaf(q2, r2b.x, fmaf(q1, r1b.x, Ab.x));
        Ab.y = fmaf(q2, r2b.y, fmaf(q1, r1b.y, Ab.y));
        Ab.z = fmaf(q2, r2b.z, fmaf(q1, r1b.z, Ab.z));
        Ab.w = fmaf(q2, r2b.w, fmaf(q1, r1b.w, Ab.w));
        __syncthreads();
    }

    // combine 8 warps: plain sums (shared fixed offset)
    float* arow = sA[w];
    arow[lane * 4 + 0] = Aa.x; arow[lane * 4 + 1] = Aa.y;
    arow[lane * 4 + 2] = Aa.z; arow[lane * 4 + 3] = Aa.w;
    arow[128 + lane * 4 + 0] = Ab.x; arow[128 + lane * 4 + 1] = Ab.y;
    arow[128 + lane * 4 + 2] = Ab.z; arow[128 + lane * 4 + 3] = Ab.w;
    if (lane == 0) sL[w] = Lsum;
    __syncthreads();

    float acc = 0.f;
    #pragma unroll
    for (int j = 0; j < 8; j++) acc += sA[j][tid];
    int pid = b * NCHUNK + chunk;
    g_PA[pid * ND + tid] = acc;
    if (tid == 0) {
        float lb = 0.f;
        #pragma unroll
        for (int j = 0; j < 8; j++) lb += sL[j];
        g_PL[pid] = lb;
    }
}

// ---------------- K3: epilogue, grid (9, NB) ------------------------------
// p < 8 : normalize alpha slice p (1024 floats, 1 float4/thread)
// p == 8: combine m from g_PA, GEMV (4 rows/warp), write ctx
__global__ void __launch_bounds__(256)
k_fin(const float* __restrict__ Wc_w, const float* __restrict__ Wc_b,
      const int* __restrict__ slen, float* __restrict__ alpha,
      float* __restrict__ out_ctx) {
    int p = blockIdx.x, b = blockIdx.y;
    int t = threadIdx.x, w = t >> 5, lane = t & 31;
    int len = slen[b];
    int len_eff = (len == 0) ? NS : len;
    float off = (len == 0) ? -10000.f : EXP_OFF;
    int nval = (len_eff + POS_PER_BLOCK - 1) / POS_PER_BLOCK;

    // every sub-block recomputes Rinv from g_PL (256B, L2-hot)
    __shared__ float sLs[NCHUNK];
    if (t < NCHUNK) sLs[t] = (t < nval) ? g_PL[b * NCHUNK + t] : 0.f;
    __syncthreads();
    float Lg = 0.f;
    #pragma unroll 8
    for (int j = 0; j < NCHUNK; j++) Lg += sLs[j];
    float Rinv = 1.f / Lg;

    if (p < 8) {
        // normalize slice p: 256 float4
        float4* a4 = (float4*)(alpha + (size_t)b * NS) + p * 256;
        int pos = (p * 256 + t) * 4;
        if (len > 0 && pos >= len) {
            a4[t] = make_float4(0.f, 0.f, 0.f, 0.f);
        } else {
            float4 e = a4[t];
            float4 o;
            o.x = (len > 0 && pos + 0 >= len) ? 0.f : __expf(e.x - off) * Rinv;
            o.y = (len > 0 && pos + 1 >= len) ? 0.f : __expf(e.y - off) * Rinv;
            o.z = (len > 0 && pos + 2 >= len) ? 0.f : __expf(e.z - off) * Rinv;
            o.w = (len > 0 && pos + 3 >= len) ? 0.f : __expf(e.w - off) * Rinv;
            a4[t] = o;
        }
        return;
    }

    // p == 8: combine + context GEMV
    __shared__ __align__(16) float sm[ND];
    float m = 0.f;
    #pragma unroll 8
    for (int j = 0; j < nval; j++)
        m += g_PA[(b * NCHUNK + j) * ND + t];
    sm[t] = m * Rinv;
    __syncthreads();

    const float4* m4 = (const float4*)sm;
    float4 ma = m4[lane], mb = m4[lane + 32];
    int d0 = w * 4;                                   // wait: 8 warps x 4 = 32 rows only
    // 8 warps x 4 rows covers 32 rows; loop 8 times for 256 rows
    #pragma unroll 1
    for (int rep = 0; rep < 8; rep++) {
        int d = rep * 32 + w * 4;
        const float4* w0 = (const float4*)(Wc_w + (size_t)(d + 0) * ND);
        const float4* w1 = (const float4*)(Wc_w + (size_t)(d + 1) * ND);
        const float4* w2 = (const float4*)(Wc_w + (size_t)(d + 2) * ND);
        const float4* w3 = (const float4*)(Wc_w + (size_t)(d + 3) * ND);
        float4 a0 = w0[lane], b0 = w0[lane + 32];     // 8 loads in flight
        float4 a1 = w1[lane], b1 = w1[lane + 32];
        float4 a2 = w2[lane], b2 = w2[lane + 32];
        float4 a3 = w3[lane], b3 = w3[lane + 32];
        float p0 = a0.x*ma.x + a0.y*ma.y + a0.z*ma.z + a0.w*ma.w
                 + b0.x*mb.x + b0.y*mb.y + b0.z*mb.z + b0.w*mb.w;
        float p1 = a1.x*ma.x + a1.y*ma.y + a1.z*ma.z + a1.w*ma.w
                 + b1.x*mb.x + b1.y*mb.y + b1.z*mb.z + b1.w*mb.w;
        float p2 = a2.x*ma.x + a2.y*ma.y + a2.z*ma.z + a2.w*ma.w
                 + b2.x*mb.x + b2.y*mb.y + b2.z*mb.z + b2.w*mb.w;
        float p3 = a3.x*ma.x + a3.y*ma.y + a3.z*ma.z + a3.w*ma.w
                 + b3.x*mb.x + b3.y*mb.y + b3.z*mb.z + b3.w*mb.w;
        #pragma unroll
        for (int o = 16; o > 0; o >>= 1) {            // 4 interleaved chains
            p0 += __shfl_xor_sync(0xffffffffu, p0, o);
            p1 += __shfl_xor_sync(0xffffffffu, p1, o);
            p2 += __shfl_xor_sync(0xffffffffu, p2, o);
            p3 += __shfl_xor_sync(0xffffffffu, p3, o);
        }
        if (lane == 0) {
            out_ctx[b * ND + d + 0] = p0 + Wc_b[d + 0];
            out_ctx[b * ND + d + 1] = p1 + Wc_b[d + 1];
            out_ctx[b * ND + d + 2] = p2 + Wc_b[d + 2];
            out_ctx[b * ND + d + 3] = p3 + Wc_b[d + 3];
        }
    }
    (void)d0;
}

// ---------------- launch ----------------
extern "C" void kernel_launch(void* const* d_in, const int* in_sizes, int n_in,
                              void* d_out, int out_size) {
    const float* hs   = (const float*)d_in[0];  // [B,S,256]
    const float* ht   = (const float*)d_in[1];  // [B,256]
    const int*   slen = (const int*)  d_in[2];  // [B]
    const float* Wa_w = (const float*)d_in[3];  // [256,256]
    const float* Wa_b = (const float*)d_in[4];  // [256]
    const float* Wc_w = (const float*)d_in[5];  // [256,256]
    const float* Wc_b = (const float*)d_in[6];  // [256]

    float* alpha = (float*)d_out;                    // [B,S]
    float* ctx   = (float*)d_out + (size_t)NB * NS;  // [B,256]

    dim3 grid1(NPRE, NB);
    k_pre<<<grid1, 256>>>(ht, Wa_w, Wa_b);
    k_pre2<<<NB, 256>>>();
    dim3 grid2(NCHUNK, NB);
    k_main<<<grid2, 256>>>(hs, slen, alpha);
    dim3 grid3(9, NB);
    k_fin<<<grid3, 256>>>(Wc_w, Wc_b, slen, alpha, ctx);
}

// round 13
// speedup vs baseline: 1.0156x; 1.0156x over previous
#include <cuda_runtime.h>
#include <math.h>
#include <stdint.h>

#define NB 32
#define NS 8192
#define ND 256
#define NCHUNK 64          // blocks per batch in main pass
#define POS_PER_BLOCK 128  // rows per block
#define TILE_ROWS 16       // rows per cp.async tile
#define NTILES (POS_PER_BLOCK / TILE_ROWS)   // 8
#define NPRE 16            // k_pre reduction split
#define EXP_OFF 48.0f      // fixed softmax offset (energies << 48+88)

// ---------------- scratch (no allocation allowed) ----------------
__device__ float g_Vp[NB * NPRE * ND];     // partial v[b] (k_pre out)
__device__ float g_V[NB * ND];             // final v[b]   (k_pre2 out)
__device__ float g_c0[NB];                 // ht[b] . Wa_b
__device__ float g_PL[NB * NCHUNK];        // per-block partial sum (fixed offset)
__device__ float g_PA[NB * NCHUNK * ND];   // per-block partial weighted row-sum
__device__ int   g_cnt[NB];                // retirement counters (reset by last block)

// ---------------- cp.async helpers ----------------
__device__ __forceinline__ void cp16(uint32_t dst, const void* src) {
    asm volatile("cp.async.cg.shared.global [%0], [%1], 16;\n" :: "r"(dst), "l"(src));
}
__device__ __forceinline__ void cp_commit() {
    asm volatile("cp.async.commit_group;\n" ::: "memory");
}
template <int N>
__device__ __forceinline__ void cp_wait() {
    asm volatile("cp.async.wait_group %0;\n" :: "n"(N) : "memory");
}

// ---------------- K1: partial v[b], c0[b] (16-way split over d) ----------
__global__ void __launch_bounds__(256)
k_pre(const float* __restrict__ ht,
      const float* __restrict__ Wa_w,
      const float* __restrict__ Wa_b) {
    int g = blockIdx.x, b = blockIdx.y, t = threadIdx.x;
    __shared__ float sh[16];
    if (t < 16) sh[t] = ht[b * ND + g * 16 + t];
    __syncthreads();
    const float* Wp = Wa_w + (size_t)(g * 16) * ND + t;
    float acc = 0.f;
    #pragma unroll
    for (int d = 0; d < 16; d++)                      // 16 loads, all in flight
        acc = fmaf(sh[d], Wp[(size_t)d * ND], acc);
    g_Vp[(b * NPRE + g) * ND + t] = acc;

    if (g == 0) {   // c0 = ht . Wa_b
        __shared__ float red[ND];
        red[t] = ht[b * ND + t] * Wa_b[t];
        __syncthreads();
        for (int s = 128; s > 0; s >>= 1) {
            if (t < s) red[t] += red[t + s];
            __syncthreads();
        }
        if (t == 0) g_c0[b] = red[0];
    }
}

// ---------------- K1b: fold 16 partials -> g_V (L2-hot, tiny) ------------
__global__ void __launch_bounds__(256)
k_pre2() {
    int b = blockIdx.x, t = threadIdx.x;
    const float* p = g_Vp + (size_t)b * NPRE * ND + t;
    float a0 = 0.f, a1 = 0.f, a2 = 0.f, a3 = 0.f;
    #pragma unroll
    for (int g = 0; g < NPRE; g += 4) {               // 16 loads in flight
        a0 += p[(g + 0) * ND];
        a1 += p[(g + 1) * ND];
        a2 += p[(g + 2) * ND];
        a3 += p[(g + 3) * ND];
    }
    g_V[b * ND + t] = (a0 + a1) + (a2 + a3);
}

// ---------------- K2: cp.async pipeline + last-block epilogue ------------
__global__ void __launch_bounds__(256, 4)
k_main(const float* __restrict__ hs, const int* __restrict__ slen,
       float* __restrict__ alpha,
       const float* __restrict__ Wc_w, const float* __restrict__ Wc_b,
       float* __restrict__ out_ctx) {
    __shared__ __align__(16) float sbuf[2][TILE_ROWS * ND];   // 2 x 16KB
    __shared__ float sA[8][ND];                                // 8KB
    __shared__ float sL[8];
    __shared__ float sE[NCHUNK];
    __shared__ int sIsLast;

    int chunk = blockIdx.x, b = blockIdx.y;
    int tid = threadIdx.x, w = tid >> 5, lane = tid & 31;
    int len = slen[b];
    int len_eff = (len == 0) ? NS : len;
    float off = (len == 0) ? -10000.f : EXP_OFF;
    int nval = (len_eff + POS_PER_BLOCK - 1) / POS_PER_BLOCK; // active chunks

    if (chunk * POS_PER_BLOCK >= len_eff) return;

    const float* gsrc = hs + ((size_t)b * NS + chunk * POS_PER_BLOCK) * ND;
    uint32_t sb = (uint32_t)__cvta_generic_to_shared(&sbuf[0][0]);

    // stage tile 0
    {
        uint32_t dst = sb;
        const char* src = (const char*)gsrc;
        #pragma unroll
        for (int k = 0; k < 4; k++)
            cp16(dst + (tid + k * 256) * 16, src + (size_t)(tid + k * 256) * 16);
        cp_commit();
    }

    // v fragments: 2 loads from final g_V (L2-hot)
    float c0 = g_c0[b];
    const float4* v4 = (const float4*)(g_V + b * ND);
    float4 va = v4[lane], vb = v4[lane + 32];

    float Lsum = 0.f;
    float4 Aa = make_float4(0.f, 0.f, 0.f, 0.f);
    float4 Ab = make_float4(0.f, 0.f, 0.f, 0.f);
    int s0 = chunk * POS_PER_BLOCK;

    #pragma unroll 1
    for (int t = 0; t < NTILES; t++) {
        if (t < NTILES - 1) {            // stage next tile into other buffer
            uint32_t dst = sb + ((t + 1) & 1) * (TILE_ROWS * ND * 4);
            const char* src = (const char*)(gsrc + (t + 1) * TILE_ROWS * ND);
            #pragma unroll
            for (int k = 0; k < 4; k++)
                cp16(dst + (tid + k * 256) * 16, src + (size_t)(tid + k * 256) * 16);
            cp_commit();
            cp_wait<1>();
        } else {
            cp_wait<0>();
        }
        __syncthreads();

        // compute: warp w handles rows 2w, 2w+1 of this tile
        const float* sp = sbuf[t & 1] + (2 * w) * ND;
        float4 r1a = ((const float4*)sp)[lane];
        float4 r1b = ((const float4*)sp)[lane + 32];
        float4 r2a = ((const float4*)sp)[64 + lane];
        float4 r2b = ((const float4*)sp)[64 + lane + 32];

        float p1 = r1a.x*va.x + r1a.y*va.y + r1a.z*va.z + r1a.w*va.w
                 + r1b.x*vb.x + r1b.y*vb.y + r1b.z*vb.z + r1b.w*vb.w;
        float p2 = r2a.x*va.x + r2a.y*va.y + r2a.z*va.z + r2a.w*va.w
                 + r2b.x*vb.x + r2b.y*vb.y + r2b.z*vb.z + r2b.w*vb.w;
        #pragma unroll
        for (int o = 16; o > 0; o >>= 1) {
            p1 += __shfl_xor_sync(0xffffffffu, p1, o);
            p2 += __shfl_xor_sync(0xffffffffu, p2, o);
        }
        int s = s0 + t * TILE_ROWS + 2 * w;
        float e1 = p1 + c0, e2 = p2 + c0;
        e1 = (e1 > 0.f) ? e1 : 0.2f * e1;            // leaky relu
        e2 = (e2 > 0.f) ? e2 : 0.2f * e2;
        if (s + 0 >= len) e1 = -10000.f;             // length mask
        if (s + 1 >= len) e2 = -10000.f;

        float q1 = __expf(e1 - off);                 // fixed offset softmax
        float q2 = __expf(e2 - off);
        if (lane == 0)                               // stage UNNORMALIZED q
            *(float2*)(alpha + (size_t)b * NS + s) = make_float2(q1, q2);
        Lsum += q1 + q2;
        Aa.x = fmaf(q2, r2a.x, fmaf(q1, r1a.x, Aa.x));
        Aa.y = fmaf(q2, r2a.y, fmaf(q1, r1a.y, Aa.y));
        Aa.z = fmaf(q2, r2a.z, fmaf(q1, r1a.z, Aa.z));
        Aa.w = fmaf(q2, r2a.w, fmaf(q1, r1a.w, Aa.w));
        Ab.x = fmaf(q2, r2b.x, fmaf(q1, r1b.x, Ab.x));
        Ab.y = fmaf(q2, r2b.y, fmaf(q1, r1b.y, Ab.y));
        Ab.z = fmaf(q2, r2b.z, fmaf(q1, r1b.z, Ab.z));
        Ab.w = fmaf(q2, r2b.w, fmaf(q1, r1b.w, Ab.w));
        __syncthreads();
    }

    // combine 8 warps: plain sums (shared fixed offset)
    float* arow = sA[w];
    arow[lane * 4 + 0] = Aa.x; arow[lane * 4 + 1] = Aa.y;
    arow[lane * 4 + 2] = Aa.z; arow[lane * 4 + 3] = Aa.w;
    arow[128 + lane * 4 + 0] = Ab.x; arow[128 + lane * 4 + 1] = Ab.y;
    arow[128 + lane * 4 + 2] = Ab.z; arow[128 + lane * 4 + 3] = Ab.w;
    if (lane == 0) sL[w] = Lsum;
    __syncthreads();

    float acc = 0.f;
    #pragma unroll
    for (int j = 0; j < 8; j++) acc += sA[j][tid];
    int pid = b * NCHUNK + chunk;
    g_PA[pid * ND + tid] = acc;
    if (tid == 0) {
        float lb = 0.f;
        #pragma unroll
        for (int j = 0; j < 8; j++) lb += sL[j];
        g_PL[pid] = lb;
    }

    // ---- retirement: last active block of batch b runs the epilogue ----
    __threadfence();
    __syncthreads();
    if (tid == 0) {
        int v = atomicAdd(&g_cnt[b], 1);
        sIsLast = (v == nval - 1);
    }
    __syncthreads();
    if (!sIsLast) return;
    __threadfence();

    // Rinv from g_PL
    if (tid < NCHUNK) sE[tid] = (tid < nval) ? g_PL[b * NCHUNK + tid] : 0.f;
    __syncthreads();
    float Lg = 0.f;
    #pragma unroll 8
    for (int j = 0; j < NCHUNK; j++) Lg += sE[j];
    float Rinv = 1.f / Lg;

    // combine m, stash normalized m in sA[0]
    float m = 0.f;
    #pragma unroll 8
    for (int j = 0; j < nval; j++)
        m += g_PA[(b * NCHUNK + j) * ND + tid];
    float* smv = sA[0];
    __syncthreads();
    smv[tid] = m * Rinv;
    __syncthreads();

    // context GEMV: 4 rows/warp, 8 reps
    const float4* m4 = (const float4*)smv;
    float4 ma = m4[lane], mb = m4[lane + 32];
    #pragma unroll 1
    for (int rep = 0; rep < 8; rep++) {
        int d = rep * 32 + w * 4;
        const float4* w0 = (const float4*)(Wc_w + (size_t)(d + 0) * ND);
        const float4* w1 = (const float4*)(Wc_w + (size_t)(d + 1) * ND);
        const float4* w2 = (const float4*)(Wc_w + (size_t)(d + 2) * ND);
        const float4* w3 = (const float4*)(Wc_w + (size_t)(d + 3) * ND);
        float4 a0 = w0[lane], b0 = w0[lane + 32];
        float4 a1 = w1[lane], b1 = w1[lane + 32];
        float4 a2 = w2[lane], b2 = w2[lane + 32];
        float4 a3 = w3[lane], b3 = w3[lane + 32];
        float p0 = a0.x*ma.x + a0.y*ma.y + a0.z*ma.z + a0.w*ma.w
                 + b0.x*mb.x + b0.y*mb.y + b0.z*mb.z + b0.w*mb.w;
        float p1 = a1.x*ma.x + a1.y*ma.y + a1.z*ma.z + a1.w*ma.w
                 + b1.x*mb.x + b1.y*mb.y + b1.z*mb.z + b1.w*mb.w;
        float p2 = a2.x*ma.x + a2.y*ma.y + a2.z*ma.z + a2.w*ma.w
                 + b2.x*mb.x + b2.y*mb.y + b2.z*mb.z + b2.w*mb.w;
        float p3 = a3.x*ma.x + a3.y*ma.y + a3.z*ma.z + a3.w*ma.w
                 + b3.x*mb.x + b3.y*mb.y + b3.z*mb.z + b3.w*mb.w;
        #pragma unroll
        for (int o = 16; o > 0; o >>= 1) {
            p0 += __shfl_xor_sync(0xffffffffu, p0, o);
            p1 += __shfl_xor_sync(0xffffffffu, p1, o);
            p2 += __shfl_xor_sync(0xffffffffu, p2, o);
            p3 += __shfl_xor_sync(0xffffffffu, p3, o);
        }
        if (lane == 0) {
            out_ctx[b * ND + d + 0] = p0 + Wc_b[d + 0];
            out_ctx[b * ND + d + 1] = p1 + Wc_b[d + 1];
            out_ctx[b * ND + d + 2] = p2 + Wc_b[d + 2];
            out_ctx[b * ND + d + 3] = p3 + Wc_b[d + 3];
        }
    }

    // normalize/zero alpha for this batch: 2048 float4, 8 per thread
    float4* a4 = (float4*)(alpha + (size_t)b * NS);
    int nwr4 = nval * 32;                // written float4s = nval*128 floats /4
    #pragma unroll
    for (int k = 0; k < 8; k++) {
        int idx = k * 256 + tid;
        if (idx >= nwr4) {
            a4[idx] = make_float4(0.f, 0.f, 0.f, 0.f);   // never-written tail
        } else {
            float4 q = a4[idx];
            q.x *= Rinv; q.y *= Rinv; q.z *= Rinv; q.w *= Rinv;
            a4[idx] = q;
        }
    }

    if (tid == 0) g_cnt[b] = 0;          // reset for next graph replay
}

// ---------------- launch ----------------
extern "C" void kernel_launch(void* const* d_in, const int* in_sizes, int n_in,
                              void* d_out, int out_size) {
    const float* hs   = (const float*)d_in[0];  // [B,S,256]
    const float* ht   = (const float*)d_in[1];  // [B,256]
    const int*   slen = (const int*)  d_in[2];  // [B]
    const float* Wa_w = (const float*)d_in[3];  // [256,256]
    const float* Wa_b = (const float*)d_in[4];  // [256]
    const float* Wc_w = (const float*)d_in[5];  // [256,256]
    const float* Wc_b = (const float*)d_in[6];  // [256]

    float* alpha = (float*)d_out;                    // [B,S]
    float* ctx   = (float*)d_out + (size_t)NB * NS;  // [B,256]

    dim3 grid1(NPRE, NB);
    k_pre<<<grid1, 256>>>(ht, Wa_w, Wa_b);
    k_pre2<<<NB, 256>>>();
    dim3 grid2(NCHUNK, NB);
    k_main<<<grid2, 256>>>(hs, slen, alpha, Wc_w, Wc_b, ctx);
}